// round 1
// baseline (speedup 1.0000x reference)
#include <cuda_runtime.h>
#include <math.h>

#define B_  4
#define S_  2048
#define D_  1024
#define H_  16
#define HS_ 64
#define M_  (B_ * S_)      // 8192 rows (b,s)
#define N3_ (3 * D_)       // 3072 fused QKV output cols

// ---------------- scratch (static device globals; no allocation) -------------
__device__ float g_Wcat[D_ * N3_];                 // [k=1024][n=3072] repacked Wq|Wk|Wv
__device__ float g_q[B_ * H_ * S_ * HS_];          // [b,h,s,e]
__device__ float g_k[B_ * H_ * S_ * HS_];
__device__ float g_v[B_ * H_ * S_ * HS_];
__device__ float g_attn[M_ * D_];                  // [b,s,d] attention output

// ---------------- 1) repack weights [H,D,HS] -> [D, 3D] ----------------------
__global__ void repack_w(const float* __restrict__ Wq,
                         const float* __restrict__ Wk,
                         const float* __restrict__ Wv) {
    int idx = blockIdx.x * blockDim.x + threadIdx.x;
    if (idx >= D_ * N3_) return;
    int d   = idx / N3_;
    int n   = idx % N3_;
    int wch = n >> 10;          // /1024
    int rem = n & 1023;
    int h   = rem >> 6;         // /64
    int e   = rem & 63;
    const float* W = (wch == 0) ? Wq : (wch == 1) ? Wk : Wv;
    g_Wcat[idx] = W[(h * D_ + d) * HS_ + e];
}

// ---------------- 2) fused QKV SGEMM: [8192,1024] x [1024,3072] --------------
// classic 128x128x8, 256 threads, 8x8 microtile
__global__ __launch_bounds__(256) void gemm_qkv(const float* __restrict__ x) {
    const int BM = 128, BN = 128, BK = 8;
    __shared__ float As[BK][BM];
    __shared__ float Bs[BK][BN];

    int bm = blockIdx.y, bn = blockIdx.x;
    int tid = threadIdx.x;

    int aRow  = tid >> 1;               // 0..127
    int aCol4 = (tid & 1) * 4;          // 0 or 4
    int bRow  = tid >> 5;               // 0..7
    int bCol4 = (tid & 31) * 4;         // 0..124

    const float* Aptr = x + (size_t)(bm * BM) * D_;
    const float* Bptr = g_Wcat + bn * BN;

    float acc[8][8];
#pragma unroll
    for (int i = 0; i < 8; i++)
#pragma unroll
        for (int j = 0; j < 8; j++) acc[i][j] = 0.f;

    int tr = (tid >> 4) * 8;            // 0..120
    int tc = (tid & 15) * 8;

    for (int k0 = 0; k0 < D_; k0 += BK) {
        float4 av = *(const float4*)(Aptr + (size_t)aRow * D_ + k0 + aCol4);
        As[aCol4 + 0][aRow] = av.x;
        As[aCol4 + 1][aRow] = av.y;
        As[aCol4 + 2][aRow] = av.z;
        As[aCol4 + 3][aRow] = av.w;
        *(float4*)&Bs[bRow][bCol4] =
            *(const float4*)(Bptr + (size_t)(k0 + bRow) * N3_ + bCol4);
        __syncthreads();

#pragma unroll
        for (int k = 0; k < BK; k++) {
            float4 a0 = *(float4*)&As[k][tr];
            float4 a1 = *(float4*)&As[k][tr + 4];
            float4 b0 = *(float4*)&Bs[k][tc];
            float4 b1 = *(float4*)&Bs[k][tc + 4];
            float ra[8] = {a0.x, a0.y, a0.z, a0.w, a1.x, a1.y, a1.z, a1.w};
            float rb[8] = {b0.x, b0.y, b0.z, b0.w, b1.x, b1.y, b1.z, b1.w};
#pragma unroll
            for (int i = 0; i < 8; i++)
#pragma unroll
                for (int j = 0; j < 8; j++) acc[i][j] += ra[i] * rb[j];
        }
        __syncthreads();
    }

    // scatter to Q/K/V scratch in [b,h,s,e] layout
    int mBase = bm * BM + tr;
    int nBase = bn * BN + tc;
#pragma unroll
    for (int i = 0; i < 8; i++) {
        int m = mBase + i;
        int b = m >> 11;                // /2048
        int s = m & 2047;
#pragma unroll
        for (int j = 0; j < 8; j++) {
            int n   = nBase + j;
            int wch = n >> 10;
            int rem = n & 1023;
            int h   = rem >> 6;
            int e   = rem & 63;
            size_t off = (size_t)(((b * H_ + h) * S_) + s) * HS_ + e;
            float* dst = (wch == 0) ? g_q : (wch == 1) ? g_k : g_v;
            dst[off] = acc[i][j];
        }
    }
}

// ---------------- 3) causal flash attention -----------------------------------
// grid (S/64, B*H), 256 threads (16x16), 64x64 tiles, HS=64
#define FA_PAD 68   // row stride (floats), keeps float4 alignment
__global__ __launch_bounds__(256) void flash_attn() {
    extern __shared__ float sm[];
    float (*Qt)[FA_PAD] = (float(*)[FA_PAD])(sm);                 // [e][r]
    float (*Kt)[FA_PAD] = (float(*)[FA_PAD])(sm + 64 * FA_PAD);   // [e][c]
    float (*Vs)[FA_PAD] = (float(*)[FA_PAD])(sm + 2 * 64 * FA_PAD); // [c][hc]
    float (*Pt)[FA_PAD] = (float(*)[FA_PAD])(sm + 3 * 64 * FA_PAD); // [c][r]

    int qb = blockIdx.x;
    int bh = blockIdx.y;
    int b  = bh >> 4;
    int h  = bh & 15;

    const float* Q = g_q + (size_t)bh * S_ * HS_;
    const float* K = g_k + (size_t)bh * S_ * HS_;
    const float* V = g_v + (size_t)bh * S_ * HS_;

    int tid = threadIdx.x;
    int ty = tid >> 4, tx = tid & 15;
    int r0 = ty * 4, c0 = tx * 4;       // c0 doubles as hc0 for the PV GEMM

    const float qk_scale = 0.125f;      // 1/sqrt(64)

    // load Q tile (scaled), transposed to [e][r]
    for (int idx = tid; idx < 64 * 64; idx += 256) {
        int r = idx >> 6, e = idx & 63;
        Qt[e][r] = Q[(size_t)(qb * 64 + r) * HS_ + e] * qk_scale;
    }

    float m_i[4], l_i[4], acc[4][4];
#pragma unroll
    for (int i = 0; i < 4; i++) {
        m_i[i] = -INFINITY; l_i[i] = 0.f;
#pragma unroll
        for (int j = 0; j < 4; j++) acc[i][j] = 0.f;
    }

    for (int kb = 0; kb <= qb; kb++) {
        __syncthreads();   // previous iteration done reading Kt/Vs/Pt
        for (int idx = tid; idx < 64 * 64; idx += 256) {
            int c = idx >> 6, e = idx & 63;
            float kv = K[(size_t)(kb * 64 + c) * HS_ + e];
            float vv = V[(size_t)(kb * 64 + c) * HS_ + e];
            Kt[e][c] = kv;
            Vs[c][e] = vv;
        }
        __syncthreads();

        // scores S = Q K^T  (4x4 per thread)
        float s[4][4];
#pragma unroll
        for (int i = 0; i < 4; i++)
#pragma unroll
            for (int j = 0; j < 4; j++) s[i][j] = 0.f;
#pragma unroll 8
        for (int e = 0; e < 64; e++) {
            float4 qv = *(float4*)&Qt[e][r0];
            float4 kv = *(float4*)&Kt[e][c0];
            float ra[4] = {qv.x, qv.y, qv.z, qv.w};
            float rb[4] = {kv.x, kv.y, kv.z, kv.w};
#pragma unroll
            for (int i = 0; i < 4; i++)
#pragma unroll
                for (int j = 0; j < 4; j++) s[i][j] += ra[i] * rb[j];
        }

        if (kb == qb) {   // causal mask on the diagonal tile
#pragma unroll
            for (int i = 0; i < 4; i++)
#pragma unroll
                for (int j = 0; j < 4; j++)
                    if (c0 + j > r0 + i) s[i][j] = -INFINITY;
        }

        // online softmax update
#pragma unroll
        for (int i = 0; i < 4; i++) {
            float mrow = fmaxf(fmaxf(s[i][0], s[i][1]), fmaxf(s[i][2], s[i][3]));
#pragma unroll
            for (int off = 8; off > 0; off >>= 1)
                mrow = fmaxf(mrow, __shfl_xor_sync(0xffffffffu, mrow, off, 16));
            float m_new = fmaxf(m_i[i], mrow);
            float alpha = __expf(m_i[i] - m_new);
            float rsum = 0.f;
#pragma unroll
            for (int j = 0; j < 4; j++) {
                float p = __expf(s[i][j] - m_new);
                s[i][j] = p;
                rsum += p;
            }
#pragma unroll
            for (int off = 8; off > 0; off >>= 1)
                rsum += __shfl_xor_sync(0xffffffffu, rsum, off, 16);
            l_i[i] = l_i[i] * alpha + rsum;
            m_i[i] = m_new;
#pragma unroll
            for (int j = 0; j < 4; j++) acc[i][j] *= alpha;
        }

        // stage P (transposed) for the PV GEMM
#pragma unroll
        for (int i = 0; i < 4; i++)
#pragma unroll
            for (int j = 0; j < 4; j++) Pt[c0 + j][r0 + i] = s[i][j];
        __syncthreads();

        // O += P @ V
#pragma unroll 8
        for (int c = 0; c < 64; c++) {
            float4 pv = *(float4*)&Pt[c][r0];
            float4 vv = *(float4*)&Vs[c][c0];
            float ra[4] = {pv.x, pv.y, pv.z, pv.w};
            float rb[4] = {vv.x, vv.y, vv.z, vv.w};
#pragma unroll
            for (int i = 0; i < 4; i++)
#pragma unroll
                for (int j = 0; j < 4; j++) acc[i][j] += ra[i] * rb[j];
        }
    }

    // write O in [b,s,d] layout (d = h*64 + hc)
#pragma unroll
    for (int i = 0; i < 4; i++) {
        float inv_l = 1.f / l_i[i];
        int srow = qb * 64 + r0 + i;
        float4 o;
        o.x = acc[i][0] * inv_l;
        o.y = acc[i][1] * inv_l;
        o.z = acc[i][2] * inv_l;
        o.w = acc[i][3] * inv_l;
        *(float4*)&g_attn[(size_t)(b * S_ + srow) * D_ + h * HS_ + c0] = o;
    }
}

// ---------------- 4) output projection + bias --------------------------------
__global__ __launch_bounds__(256) void gemm_out(const float* __restrict__ Wo,
                                                const float* __restrict__ bo,
                                                float* __restrict__ out) {
    const int BM = 128, BN = 128, BK = 8;
    __shared__ float As[BK][BM];
    __shared__ float Bs[BK][BN];

    int bm = blockIdx.y, bn = blockIdx.x;
    int tid = threadIdx.x;

    int aRow  = tid >> 1;
    int aCol4 = (tid & 1) * 4;
    int bRow  = tid >> 5;
    int bCol4 = (tid & 31) * 4;

    const float* Aptr = g_attn + (size_t)(bm * BM) * D_;
    const float* Bptr = Wo + bn * BN;

    float acc[8][8];
#pragma unroll
    for (int i = 0; i < 8; i++)
#pragma unroll
        for (int j = 0; j < 8; j++) acc[i][j] = 0.f;

    int tr = (tid >> 4) * 8;
    int tc = (tid & 15) * 8;

    for (int k0 = 0; k0 < D_; k0 += BK) {
        float4 av = *(const float4*)(Aptr + (size_t)aRow * D_ + k0 + aCol4);
        As[aCol4 + 0][aRow] = av.x;
        As[aCol4 + 1][aRow] = av.y;
        As[aCol4 + 2][aRow] = av.z;
        As[aCol4 + 3][aRow] = av.w;
        *(float4*)&Bs[bRow][bCol4] =
            *(const float4*)(Bptr + (size_t)(k0 + bRow) * D_ + bCol4);
        __syncthreads();

#pragma unroll
        for (int k = 0; k < BK; k++) {
            float4 a0 = *(float4*)&As[k][tr];
            float4 a1 = *(float4*)&As[k][tr + 4];
            float4 b0 = *(float4*)&Bs[k][tc];
            float4 b1 = *(float4*)&Bs[k][tc + 4];
            float ra[8] = {a0.x, a0.y, a0.z, a0.w, a1.x, a1.y, a1.z, a1.w};
            float rb[8] = {b0.x, b0.y, b0.z, b0.w, b1.x, b1.y, b1.z, b1.w};
#pragma unroll
            for (int i = 0; i < 8; i++)
#pragma unroll
                for (int j = 0; j < 8; j++) acc[i][j] += ra[i] * rb[j];
        }
        __syncthreads();
    }

    int mBase = bm * BM + tr;
    int nBase = bn * BN + tc;
#pragma unroll
    for (int i = 0; i < 8; i++) {
        float* row = out + (size_t)(mBase + i) * D_ + nBase;
#pragma unroll
        for (int j = 0; j < 8; j += 4) {
            float4 o;
            o.x = acc[i][j + 0] + bo[nBase + j + 0];
            o.y = acc[i][j + 1] + bo[nBase + j + 1];
            o.z = acc[i][j + 2] + bo[nBase + j + 2];
            o.w = acc[i][j + 3] + bo[nBase + j + 3];
            *(float4*)(row + j) = o;
        }
    }
}

// ---------------- launch ------------------------------------------------------
extern "C" void kernel_launch(void* const* d_in, const int* in_sizes, int n_in,
                              void* d_out, int out_size) {
    const float* x  = (const float*)d_in[0];
    const float* Wq = (const float*)d_in[1];
    const float* Wk = (const float*)d_in[2];
    const float* Wv = (const float*)d_in[3];
    const float* Wo = (const float*)d_in[4];
    const float* bo = (const float*)d_in[5];
    float* out = (float*)d_out;

    // 1) repack QKV weights into [D, 3D]
    {
        int total = D_ * N3_;
        repack_w<<<(total + 255) / 256, 256>>>(Wq, Wk, Wv);
    }
    // 2) fused QKV projection
    {
        dim3 grid(N3_ / 128, M_ / 128);
        gemm_qkv<<<grid, 256>>>(x);
    }
    // 3) causal flash attention
    {
        int smem = 4 * 64 * FA_PAD * sizeof(float);   // 69632 B
        cudaFuncSetAttribute(flash_attn,
                             cudaFuncAttributeMaxDynamicSharedMemorySize, smem);
        dim3 grid(S_ / 64, B_ * H_);
        flash_attn<<<grid, 256, smem>>>();
    }
    // 4) output projection + bias
    {
        dim3 grid(D_ / 128, M_ / 128);
        gemm_out<<<grid, 256>>>(Wo, bo, out);
    }
}